// round 6
// baseline (speedup 1.0000x reference)
#include <cuda_runtime.h>
#include <cuda_fp16.h>
#include <cstdint>

// ---------------------------------------------------------------------------
// SynapticPlasticityModule on GB300 — mma.sync fp16 GEMM, 64x64 warp tiles,
// double-buffered cp.async, fused column-sum epilogue.
// Outputs (d_out, fp32): [output B*H][new_w H*H][new_meta H][hist ACT]
// ---------------------------------------------------------------------------

#define H_DIM 1024
#define B_DIM 16384
#define HIST_LEN 100
#define SPLITX 256
#define MTILES (B_DIM / 128)

#define TM 128
#define TN 128
#define KC 64
#define NCHUNK (H_DIM / KC)                 // 16
#define STAGE_BYTES (TM * 128 + TN * 128)   // 32768
#define GEMM_SMEM (2 * STAGE_BYTES)         // 65536
#define GTHREADS 128                        // 4 warps, 64x64 each

// __device__ scratch (allocation-free rule: static module storage)
__device__ __half g_xh[(size_t)B_DIM * H_DIM];
__device__ __half g_wh[(size_t)H_DIM * H_DIM];
__device__ float  g_xpart[SPLITX * H_DIM];
__device__ float  g_opart[MTILES * H_DIM];
__device__ float  g_xmean[H_DIM];
__device__ float  g_omean[H_DIM];
__device__ float  g_a[H_DIM];
__device__ float  g_b[H_DIM];
__device__ float  g_scal[2];

__device__ __forceinline__ uint32_t smem_u32(const void* p) {
    uint32_t a;
    asm("{ .reg .u64 t; cvta.to.shared.u64 t, %1; cvt.u32.u64 %0, t; }"
        : "=r"(a) : "l"(p));
    return a;
}
#define SW128(off) ((off) ^ (((off) >> 3) & 0x70))

#define CP_ASYNC16(smem_addr, gptr) \
    asm volatile("cp.async.cg.shared.global [%0], [%1], 16;" \
                 :: "r"(smem_addr), "l"(gptr) : "memory")
#define CP_COMMIT() asm volatile("cp.async.commit_group;" ::: "memory")
#define CP_WAIT1()  asm volatile("cp.async.wait_group 1;" ::: "memory")
#define CP_WAIT0()  asm volatile("cp.async.wait_group 0;" ::: "memory")

__device__ __forceinline__ void ldmx4(uint32_t* r, uint32_t addr) {
    asm volatile("ldmatrix.sync.aligned.m8n8.x4.shared.b16 {%0,%1,%2,%3}, [%4];"
                 : "=r"(r[0]), "=r"(r[1]), "=r"(r[2]), "=r"(r[3]) : "r"(addr));
}
__device__ __forceinline__ void mma16816(float* d, const uint32_t* a,
                                         const uint32_t* b) {
    asm volatile(
        "mma.sync.aligned.m16n8k16.row.col.f32.f16.f16.f32 "
        "{%0,%1,%2,%3}, {%4,%5,%6,%7}, {%8,%9}, {%0,%1,%2,%3};"
        : "+f"(d[0]), "+f"(d[1]), "+f"(d[2]), "+f"(d[3])
        : "r"(a[0]), "r"(a[1]), "r"(a[2]), "r"(a[3]), "r"(b[0]), "r"(b[1]));
}

// ---------------------------------------------------------------------------
__global__ __launch_bounds__(256) void convert_x(const float* __restrict__ x)
{
    const int rows_per = B_DIM / SPLITX;     // 64
    const int c4 = threadIdx.x * 4;
    const size_t row0 = (size_t)blockIdx.y * rows_per;

    float4 s = make_float4(0.f, 0.f, 0.f, 0.f);
    const float* p = x + row0 * H_DIM + c4;
    __half* q = g_xh + row0 * H_DIM + c4;

#pragma unroll 4
    for (int r = 0; r < rows_per; r++) {
        float4 v = *reinterpret_cast<const float4*>(p + (size_t)r * H_DIM);
        s.x += v.x; s.y += v.y; s.z += v.z; s.w += v.w;
        __half2 h01 = __floats2half2_rn(v.x, v.y);
        __half2 h23 = __floats2half2_rn(v.z, v.w);
        *reinterpret_cast<uint2*>(q + (size_t)r * H_DIM) =
            make_uint2(*reinterpret_cast<uint32_t*>(&h01),
                       *reinterpret_cast<uint32_t*>(&h23));
    }
    *reinterpret_cast<float4*>(g_xpart + blockIdx.y * H_DIM + c4) = s;
}

__global__ __launch_bounds__(256) void reduce_x(float invB)
{
    int h = blockIdx.x * 256 + threadIdx.x;
    float s = 0.0f;
    for (int i = 0; i < SPLITX; i++) s += g_xpart[i * H_DIM + h];
    g_xmean[h] = s * invB;
}

__global__ void convert_w(const float* __restrict__ W, const float* __restrict__ meta)
{
    __shared__ float tile[32][33];
    int n0 = blockIdx.x * 32, k0 = blockIdx.y * 32;
    int tx = threadIdx.x, ty = threadIdx.y;
#pragma unroll
    for (int i = ty; i < 32; i += 8)
        tile[i][tx] = W[(size_t)(k0 + i) * H_DIM + n0 + tx] * meta[n0 + tx];
    __syncthreads();
#pragma unroll
    for (int i = ty; i < 32; i += 8)
        g_wh[(size_t)(n0 + i) * H_DIM + k0 + tx] = __float2half_rn(tile[tx][i]);
}

// ---------------------------------------------------------------------------
// GEMM: C[M,N] = A[M,K] @ B[N,K]^T (fp16 in, fp32 out) + fused column sums.
// 128x128 CTA tile, 4 warps of 64x64, double-buffered cp.async.
// ---------------------------------------------------------------------------
__global__ __launch_bounds__(GTHREADS, 2) void gemm_mma(float* __restrict__ C)
{
    extern __shared__ char smem[];
    const uint32_t sb = smem_u32(smem);
    const int tid  = threadIdx.x;
    const int wid  = tid >> 5;
    const int lane = tid & 31;
    const int m0 = blockIdx.y * TM;
    const int n0 = blockIdx.x * TN;
    const int m_w = (wid >> 1) * 64;
    const int n_w = (wid & 1) * 64;

    float acc[4][8][4];
#pragma unroll
    for (int i = 0; i < 4; i++)
#pragma unroll
        for (int j = 0; j < 8; j++)
#pragma unroll
            for (int q = 0; q < 4; q++) acc[i][j][q] = 0.0f;

    // load mapping: 128 threads -> 16 rows x 8 segments per iteration
    const int lrow = tid >> 3;   // 0..15
    const int lseg = tid & 7;    // 0..7
    const __half* gA = g_xh + (size_t)(m0 + lrow) * H_DIM + lseg * 8;
    const __half* gB = g_wh + (size_t)(n0 + lrow) * H_DIM + lseg * 8;

#define LOAD_STAGE(c, s) do {                                                  \
    const uint32_t base = sb + (s) * STAGE_BYTES;                              \
    const int koff = (c) * KC;                                                 \
    _Pragma("unroll")                                                          \
    for (int it = 0; it < 8; it++) {                                           \
        int row = it * 16 + lrow;                                              \
        uint32_t off = SW128((uint32_t)(row * 128 + lseg * 16));               \
        CP_ASYNC16(base + off, gA + (size_t)it * 16 * H_DIM + koff);           \
    }                                                                          \
    _Pragma("unroll")                                                          \
    for (int it = 0; it < 8; it++) {                                           \
        int row = it * 16 + lrow;                                              \
        uint32_t off = SW128((uint32_t)(row * 128 + lseg * 16));               \
        CP_ASYNC16(base + TM * 128 + off, gB + (size_t)it * 16 * H_DIM + koff);\
    }                                                                          \
} while (0)

    LOAD_STAGE(0, 0);
    CP_COMMIT();

    const int a_row = m_w + (lane & 15);                          // + mi*16
    const int a_colb = (lane >> 4) << 4;
    const int b_row = n_w + (lane & 7) + ((lane >> 4) & 1) * 8;   // + bq*16
    const int b_colb = ((lane >> 3) & 1) << 4;

    for (int c = 0; c < NCHUNK; c++) {
        if (c + 1 < NCHUNK) {
            LOAD_STAGE(c + 1, (c + 1) & 1);
            CP_COMMIT();
            CP_WAIT1();
        } else {
            CP_WAIT0();
        }
        __syncthreads();

        const uint32_t baseA = sb + (c & 1) * STAGE_BYTES;
        const uint32_t baseB = baseA + TM * 128;

#pragma unroll
        for (int ks = 0; ks < KC / 16; ks++) {
            uint32_t a[4][4], b[4][4];
#pragma unroll
            for (int mi = 0; mi < 4; mi++) {
                uint32_t off = (uint32_t)((a_row + mi * 16) * 128 + ks * 32 + a_colb);
                ldmx4(a[mi], baseA + SW128(off));
            }
#pragma unroll
            for (int bq = 0; bq < 4; bq++) {
                uint32_t off = (uint32_t)((b_row + bq * 16) * 128 + ks * 32 + b_colb);
                ldmx4(b[bq], baseB + SW128(off));
            }
#pragma unroll
            for (int mi = 0; mi < 4; mi++)
#pragma unroll
                for (int bq = 0; bq < 4; bq++) {
                    mma16816(acc[mi][bq * 2 + 0], a[mi], &b[bq][0]);
                    mma16816(acc[mi][bq * 2 + 1], a[mi], &b[bq][2]);
                }
        }
        __syncthreads();
    }

    // ---- epilogue 1: store C tile
    const int g = lane >> 2, tig = lane & 3;
#pragma unroll
    for (int mi = 0; mi < 4; mi++) {
        const size_t r0 = (size_t)(m0 + m_w + mi * 16 + g);
#pragma unroll
        for (int ni = 0; ni < 8; ni++) {
            const int col = n0 + n_w + ni * 8 + tig * 2;
            *reinterpret_cast<float2*>(C + r0 * H_DIM + col) =
                make_float2(acc[mi][ni][0], acc[mi][ni][1]);
            *reinterpret_cast<float2*>(C + (r0 + 8) * H_DIM + col) =
                make_float2(acc[mi][ni][2], acc[mi][ni][3]);
        }
    }

    // ---- epilogue 2: fused column sums -> g_opart[blockIdx.y]
    float* red = reinterpret_cast<float*>(smem);   // 2 * 128 floats
#pragma unroll
    for (int ni = 0; ni < 8; ni++) {
        float s0 = 0.f, s1 = 0.f;
#pragma unroll
        for (int mi = 0; mi < 4; mi++) {
            s0 += acc[mi][ni][0] + acc[mi][ni][2];
            s1 += acc[mi][ni][1] + acc[mi][ni][3];
        }
#pragma unroll
        for (int o = 4; o < 32; o <<= 1) {
            s0 += __shfl_xor_sync(0xffffffffu, s0, o);
            s1 += __shfl_xor_sync(0xffffffffu, s1, o);
        }
        if (lane < 4) {
            int col = n_w + ni * 8 + lane * 2;
            red[(wid >> 1) * 128 + col]     = s0;
            red[(wid >> 1) * 128 + col + 1] = s1;
        }
    }
    __syncthreads();
    if (tid < 128) {
        g_opart[(size_t)blockIdx.y * H_DIM + n0 + tid] = red[tid] + red[128 + tid];
    }
#undef LOAD_STAGE
}

// ---------------------------------------------------------------------------
__global__ __launch_bounds__(256) void reduce_o_stdp(
    const float* __restrict__ pre_hist, const float* __restrict__ post_hist,
    const float* __restrict__ d_win, const float* __restrict__ d_dec, float invB)
{
    int h = blockIdx.x * 256 + threadIdx.x;
    float s = 0.0f;
    for (int i = 0; i < MTILES; i++) s += g_opart[i * H_DIM + h];
    float om = s * invB;
    g_omean[h] = om;

    float win = *d_win, dec = *d_dec;
    float a = 0.0f, b = 0.0f;
    for (int i = 0; i < 99; i++) {
        float dt = (float)(HIST_LEN - i) * win;
        float wv = 0.01f * expf(-dt * dec);
        a += wv * pre_hist[(i + 1) * H_DIM + h];
        if (i >= 1) b += wv * post_hist[(i + 1) * H_DIM + h];
    }
    float w99 = 0.01f * expf(-(1.0f * win) * dec);
    b += w99 * om;
    g_a[h] = a;
    g_b[h] = b;
}

__global__ __launch_bounds__(256) void scalars_kernel(
    const float* __restrict__ act, const int* __restrict__ d_ptr,
    const float* __restrict__ d_target, const float* __restrict__ d_hrate,
    float* __restrict__ out_hist, int act_len)
{
    __shared__ float red[256];
    int tid = threadIdx.x;

    float s = 0.0f;
    for (int h = tid; h < H_DIM; h += 256) s += g_omean[h];
    red[tid] = s;
    __syncthreads();
    for (int o = 128; o > 0; o >>= 1) {
        if (tid < o) red[tid] += red[tid + o];
        __syncthreads();
    }
    float m = red[0] / (float)H_DIM;
    __syncthreads();

    float as = 0.0f;
    for (int i = tid; i < act_len; i += 256) as += act[i];
    red[tid] = as;
    __syncthreads();
    for (int o = 128; o > 0; o >>= 1) {
        if (tid < o) red[tid] += red[tid + o];
        __syncthreads();
    }
    int ptr = *d_ptr;
    float hist_mean = (red[0] - act[ptr] + m) / (float)act_len;
    float factor = 1.0f + (*d_hrate) * ((*d_target) - hist_mean);

    if (tid == 0) { g_scal[0] = m; g_scal[1] = factor; }

    for (int i = tid; i < act_len; i += 256)
        out_hist[i] = (i == ptr) ? m : act[i];
}

__global__ __launch_bounds__(256) void weights_meta_kernel(
    const float* __restrict__ W, const float* __restrict__ meta,
    const float* __restrict__ d_mlr,
    float* __restrict__ out_w, float* __restrict__ out_meta)
{
    size_t idx = (size_t)blockIdx.x * 256 + threadIdx.x;
    int r = (int)(idx >> 10);
    int c = (int)(idx & (H_DIM - 1));
    float factor = g_scal[1];
    float v = W[idx] + g_omean[r] * g_a[c] - g_b[r] * g_xmean[c];
    v = fminf(fmaxf(v, -1.0f), 1.0f);
    v *= factor;
    v = fminf(fmaxf(v, -1.0f), 1.0f);
    out_w[idx] = v;

    if (idx < H_DIM) {
        float mlr = *d_mlr;
        float mv = meta[idx] + mlr * (g_omean[idx] - meta[idx]);
        out_meta[idx] = fminf(fmaxf(mv, 0.0f), 2.0f);
    }
}

// ---------------------------------------------------------------------------
extern "C" void kernel_launch(void* const* d_in, const int* in_sizes, int n_in,
                              void* d_out, int out_size)
{
    const float* x      = (const float*)d_in[0];
    const float* W      = (const float*)d_in[1];
    const float* meta   = (const float*)d_in[2];
    const float* pre    = (const float*)d_in[3];
    const float* post   = (const float*)d_in[4];
    const float* act    = (const float*)d_in[5];
    const int*   ptr    = (const int*)d_in[6];
    const float* win    = (const float*)d_in[7];
    const float* dec    = (const float*)d_in[8];
    const float* target = (const float*)d_in[9];
    const float* hrate  = (const float*)d_in[10];
    const float* mlr    = (const float*)d_in[11];

    const int H = H_DIM;
    const int B = in_sizes[0] / H;       // 16384
    const int ACT = in_sizes[5];         // 1000

    float* out      = (float*)d_out;
    float* out_w    = out + (size_t)B * H;
    float* out_meta = out_w + (size_t)H * H;
    float* out_hist = out_meta + H;

    const float invB = 1.0f / (float)B;

    static bool attr_done = false;
    if (!attr_done) {
        cudaFuncSetAttribute(gemm_mma, cudaFuncAttributeMaxDynamicSharedMemorySize,
                             GEMM_SMEM);
        attr_done = true;
    }

    convert_x<<<dim3(1, SPLITX), 256>>>(x);
    convert_w<<<dim3(32, 32), dim3(32, 8)>>>(W, meta);
    reduce_x<<<H / 256, 256>>>(invB);

    dim3 ggrid(H / TN, B / TM);
    gemm_mma<<<ggrid, GTHREADS, GEMM_SMEM>>>(out);

    reduce_o_stdp<<<H / 256, 256>>>(pre, post, win, dec, invB);
    scalars_kernel<<<1, 256>>>(act, ptr, target, hrate, out_hist, ACT);
    weights_meta_kernel<<<(H * H) / 256, 256>>>(W, meta, mlr, out_w, out_meta);
}

// round 7
// speedup vs baseline: 1.0451x; 1.0451x over previous
#include <cuda_runtime.h>
#include <cuda_fp16.h>
#include <cstdint>

// ---------------------------------------------------------------------------
// SynapticPlasticityModule on GB300 — mma.sync fp16 GEMM (round-4 best config)
// + merged pre/post kernels.
// Outputs (d_out, fp32): [output B*H][new_w H*H][new_meta H][hist ACT]
// ---------------------------------------------------------------------------

#define H_DIM 1024
#define B_DIM 16384
#define HIST_LEN 100
#define SPLITX 512
#define MTILES (B_DIM / 128)

#define TM 128
#define TN 128
#define KC 64
#define NCHUNK (H_DIM / KC)                 // 16
#define STAGE_BYTES (TM * 128 + TN * 128)   // 32768
#define GEMM_SMEM (2 * STAGE_BYTES)         // 65536

// __device__ scratch (allocation-free rule: static module storage)
__device__ __half g_xh[(size_t)B_DIM * H_DIM];
__device__ __half g_wh[(size_t)H_DIM * H_DIM];
__device__ float  g_xpart[SPLITX * H_DIM];
__device__ float  g_opart[MTILES * H_DIM];
__device__ float  g_xmean[H_DIM];
__device__ float  g_omean[H_DIM];
__device__ float  g_a[H_DIM];
__device__ float  g_b[H_DIM];
__device__ float  g_scal[2];

__device__ __forceinline__ uint32_t smem_u32(const void* p) {
    uint32_t a;
    asm("{ .reg .u64 t; cvta.to.shared.u64 t, %1; cvt.u32.u64 %0, t; }"
        : "=r"(a) : "l"(p));
    return a;
}
#define SW128(off) ((off) ^ (((off) >> 3) & 0x70))

#define CP_ASYNC16(smem_addr, gptr) \
    asm volatile("cp.async.cg.shared.global [%0], [%1], 16;" \
                 :: "r"(smem_addr), "l"(gptr) : "memory")
#define CP_COMMIT() asm volatile("cp.async.commit_group;" ::: "memory")
#define CP_WAIT1()  asm volatile("cp.async.wait_group 1;" ::: "memory")
#define CP_WAIT0()  asm volatile("cp.async.wait_group 0;" ::: "memory")

__device__ __forceinline__ void ldmx4(uint32_t* r, uint32_t addr) {
    asm volatile("ldmatrix.sync.aligned.m8n8.x4.shared.b16 {%0,%1,%2,%3}, [%4];"
                 : "=r"(r[0]), "=r"(r[1]), "=r"(r[2]), "=r"(r[3]) : "r"(addr));
}
__device__ __forceinline__ void mma16816(float* d, const uint32_t* a,
                                         const uint32_t* b) {
    asm volatile(
        "mma.sync.aligned.m16n8k16.row.col.f32.f16.f16.f32 "
        "{%0,%1,%2,%3}, {%4,%5,%6,%7}, {%8,%9}, {%0,%1,%2,%3};"
        : "+f"(d[0]), "+f"(d[1]), "+f"(d[2]), "+f"(d[3])
        : "r"(a[0]), "r"(a[1]), "r"(a[2]), "r"(a[3]), "r"(b[0]), "r"(b[1]));
}

// ---------------------------------------------------------------------------
// convert_fused: blocks [0, SPLITX) convert x + column partials;
// blocks [SPLITX, SPLITX+1024) transpose-scale W into g_wh.
// ---------------------------------------------------------------------------
__global__ __launch_bounds__(256) void convert_fused(
    const float* __restrict__ x, const float* __restrict__ W,
    const float* __restrict__ meta)
{
    __shared__ float tile[32][33];

    if (blockIdx.y < SPLITX) {
        const int rows_per = B_DIM / SPLITX;     // 32
        const int c4 = threadIdx.x * 4;
        const size_t row0 = (size_t)blockIdx.y * rows_per;

        float4 s = make_float4(0.f, 0.f, 0.f, 0.f);
        const float* p = x + row0 * H_DIM + c4;
        __half* q = g_xh + row0 * H_DIM + c4;

#pragma unroll 8
        for (int r = 0; r < rows_per; r++) {
            float4 v = __ldcs(reinterpret_cast<const float4*>(p + (size_t)r * H_DIM));
            s.x += v.x; s.y += v.y; s.z += v.z; s.w += v.w;
            __half2 h01 = __floats2half2_rn(v.x, v.y);
            __half2 h23 = __floats2half2_rn(v.z, v.w);
            *reinterpret_cast<uint2*>(q + (size_t)r * H_DIM) =
                make_uint2(*reinterpret_cast<uint32_t*>(&h01),
                           *reinterpret_cast<uint32_t*>(&h23));
        }
        *reinterpret_cast<float4*>(g_xpart + blockIdx.y * H_DIM + c4) = s;
    } else {
        const int wb = blockIdx.y - SPLITX;           // 0..1023
        const int n0 = (wb & 31) * 32;
        const int k0 = (wb >> 5) * 32;
        const int tx = threadIdx.x & 31;
        const int ty = threadIdx.x >> 5;              // 0..7
#pragma unroll
        for (int i = ty; i < 32; i += 8)
            tile[i][tx] = W[(size_t)(k0 + i) * H_DIM + n0 + tx] * meta[n0 + tx];
        __syncthreads();
#pragma unroll
        for (int i = ty; i < 32; i += 8)
            g_wh[(size_t)(n0 + i) * H_DIM + k0 + tx] = __float2half_rn(tile[tx][i]);
    }
}

// ---------------------------------------------------------------------------
// GEMM: C[M,N] = A[M,K] @ B[N,K]^T (fp16 in, fp32 out) + fused column sums.
// Round-4 best config: 128x128 CTA, 8 warps of 32x64, 2-stage cp.async.
// ---------------------------------------------------------------------------
__global__ __launch_bounds__(256, 2) void gemm_mma(float* __restrict__ C)
{
    extern __shared__ char smem[];
    const uint32_t sb = smem_u32(smem);
    const int tid  = threadIdx.x;
    const int wid  = tid >> 5;
    const int lane = tid & 31;
    const int m0 = blockIdx.y * TM;
    const int n0 = blockIdx.x * TN;
    const int m_w = (wid & 3) * 32;
    const int n_w = (wid >> 2) * 64;

    float acc[2][8][4];
#pragma unroll
    for (int i = 0; i < 2; i++)
#pragma unroll
        for (int j = 0; j < 8; j++)
#pragma unroll
            for (int q = 0; q < 4; q++) acc[i][j][q] = 0.0f;

    const int lrow = tid >> 3;
    const int lseg = tid & 7;
    const __half* gA = g_xh + (size_t)(m0 + lrow) * H_DIM + lseg * 8;
    const __half* gB = g_wh + (size_t)(n0 + lrow) * H_DIM + lseg * 8;

#define LOAD_STAGE(c, s) do {                                                  \
    const uint32_t base = sb + (s) * STAGE_BYTES;                              \
    const int koff = (c) * KC;                                                 \
    _Pragma("unroll")                                                          \
    for (int it = 0; it < 4; it++) {                                           \
        int row = it * 32 + lrow;                                              \
        uint32_t off = SW128((uint32_t)(row * 128 + lseg * 16));               \
        CP_ASYNC16(base + off, gA + (size_t)it * 32 * H_DIM + koff);           \
    }                                                                          \
    _Pragma("unroll")                                                          \
    for (int it = 0; it < 4; it++) {                                           \
        int row = it * 32 + lrow;                                              \
        uint32_t off = SW128((uint32_t)(row * 128 + lseg * 16));               \
        CP_ASYNC16(base + TM * 128 + off, gB + (size_t)it * 32 * H_DIM + koff);\
    }                                                                          \
} while (0)

    LOAD_STAGE(0, 0);
    CP_COMMIT();

    const int a_row = m_w + (lane & 15);
    const int a_colb = (lane >> 4) << 4;
    const int b_row = n_w + (lane & 7) + ((lane >> 4) & 1) * 8;
    const int b_colb = ((lane >> 3) & 1) << 4;

    for (int c = 0; c < NCHUNK; c++) {
        if (c + 1 < NCHUNK) {
            LOAD_STAGE(c + 1, (c + 1) & 1);
            CP_COMMIT();
            CP_WAIT1();
        } else {
            CP_WAIT0();
        }
        __syncthreads();

        const uint32_t baseA = sb + (c & 1) * STAGE_BYTES;
        const uint32_t baseB = baseA + TM * 128;

#pragma unroll
        for (int ks = 0; ks < KC / 16; ks++) {
            uint32_t a[2][4], b[4][4];
#pragma unroll
            for (int mi = 0; mi < 2; mi++) {
                uint32_t off = (uint32_t)((a_row + mi * 16) * 128 + ks * 32 + a_colb);
                ldmx4(a[mi], baseA + SW128(off));
            }
#pragma unroll
            for (int bq = 0; bq < 4; bq++) {
                uint32_t off = (uint32_t)((b_row + bq * 16) * 128 + ks * 32 + b_colb);
                ldmx4(b[bq], baseB + SW128(off));
            }
#pragma unroll
            for (int mi = 0; mi < 2; mi++)
#pragma unroll
                for (int bq = 0; bq < 4; bq++) {
                    mma16816(acc[mi][bq * 2 + 0], a[mi], &b[bq][0]);
                    mma16816(acc[mi][bq * 2 + 1], a[mi], &b[bq][2]);
                }
        }
        __syncthreads();
    }

    // ---- epilogue 1: store C tile
    const int g = lane >> 2, tig = lane & 3;
#pragma unroll
    for (int mi = 0; mi < 2; mi++) {
        const size_t r0 = (size_t)(m0 + m_w + mi * 16 + g);
#pragma unroll
        for (int ni = 0; ni < 8; ni++) {
            const int col = n0 + n_w + ni * 8 + tig * 2;
            *reinterpret_cast<float2*>(C + r0 * H_DIM + col) =
                make_float2(acc[mi][ni][0], acc[mi][ni][1]);
            *reinterpret_cast<float2*>(C + (r0 + 8) * H_DIM + col) =
                make_float2(acc[mi][ni][2], acc[mi][ni][3]);
        }
    }

    // ---- epilogue 2: fused column sums -> g_opart[blockIdx.y]
    float* red = reinterpret_cast<float*>(smem);
#pragma unroll
    for (int ni = 0; ni < 8; ni++) {
        float s0 = acc[0][ni][0] + acc[0][ni][2] + acc[1][ni][0] + acc[1][ni][2];
        float s1 = acc[0][ni][1] + acc[0][ni][3] + acc[1][ni][1] + acc[1][ni][3];
#pragma unroll
        for (int o = 4; o < 32; o <<= 1) {
            s0 += __shfl_xor_sync(0xffffffffu, s0, o);
            s1 += __shfl_xor_sync(0xffffffffu, s1, o);
        }
        if (lane < 4) {
            int col = n_w + ni * 8 + lane * 2;
            red[(wid & 3) * 128 + col]     = s0;
            red[(wid & 3) * 128 + col + 1] = s1;
        }
    }
    __syncthreads();
    if (tid < 128) {
        float s = red[tid] + red[128 + tid] + red[256 + tid] + red[384 + tid];
        g_opart[(size_t)blockIdx.y * H_DIM + n0 + tid] = s;
    }
#undef LOAD_STAGE
}

// ---------------------------------------------------------------------------
// reduce xmean + omean + STDP weighted history sums.  grid H/256.
// ---------------------------------------------------------------------------
__global__ __launch_bounds__(256) void reduce_o_stdp(
    const float* __restrict__ pre_hist, const float* __restrict__ post_hist,
    const float* __restrict__ d_win, const float* __restrict__ d_dec, float invB)
{
    int h = blockIdx.x * 256 + threadIdx.x;

    float sx = 0.0f;
    for (int i = 0; i < SPLITX; i++) sx += g_xpart[i * H_DIM + h];
    g_xmean[h] = sx * invB;

    float s = 0.0f;
    for (int i = 0; i < MTILES; i++) s += g_opart[i * H_DIM + h];
    float om = s * invB;
    g_omean[h] = om;

    float win = *d_win, dec = *d_dec;
    float a = 0.0f, b = 0.0f;
    for (int i = 0; i < 99; i++) {
        float dt = (float)(HIST_LEN - i) * win;
        float wv = 0.01f * expf(-dt * dec);
        a += wv * pre_hist[(i + 1) * H_DIM + h];
        if (i >= 1) b += wv * post_hist[(i + 1) * H_DIM + h];
    }
    float w99 = 0.01f * expf(-(1.0f * win) * dec);
    b += w99 * om;
    g_a[h] = a;
    g_b[h] = b;
}

__global__ __launch_bounds__(256) void scalars_kernel(
    const float* __restrict__ act, const int* __restrict__ d_ptr,
    const float* __restrict__ d_target, const float* __restrict__ d_hrate,
    float* __restrict__ out_hist, int act_len)
{
    __shared__ float red[256];
    int tid = threadIdx.x;

    float s = 0.0f;
    for (int h = tid; h < H_DIM; h += 256) s += g_omean[h];
    red[tid] = s;
    __syncthreads();
    for (int o = 128; o > 0; o >>= 1) {
        if (tid < o) red[tid] += red[tid + o];
        __syncthreads();
    }
    float m = red[0] / (float)H_DIM;
    __syncthreads();

    float as = 0.0f;
    for (int i = tid; i < act_len; i += 256) as += act[i];
    red[tid] = as;
    __syncthreads();
    for (int o = 128; o > 0; o >>= 1) {
        if (tid < o) red[tid] += red[tid + o];
        __syncthreads();
    }
    int ptr = *d_ptr;
    float hist_mean = (red[0] - act[ptr] + m) / (float)act_len;
    float factor = 1.0f + (*d_hrate) * ((*d_target) - hist_mean);

    if (tid == 0) { g_scal[0] = m; g_scal[1] = factor; }

    for (int i = tid; i < act_len; i += 256)
        out_hist[i] = (i == ptr) ? m : act[i];
}

// weights (float4) + meta fused. grid = H*H/(256*4)
__global__ __launch_bounds__(256) void weights_meta_kernel(
    const float* __restrict__ W, const float* __restrict__ meta,
    const float* __restrict__ d_mlr,
    float* __restrict__ out_w, float* __restrict__ out_meta)
{
    size_t i4 = (size_t)blockIdx.x * 256 + threadIdx.x;   // float4 index
    size_t base = i4 * 4;
    int r = (int)(base >> 10);
    int c = (int)(base & (H_DIM - 1));
    float factor = g_scal[1];
    float om = g_omean[r], gb = g_b[r];

    float4 w  = *reinterpret_cast<const float4*>(W + base);
    float4 ga = *reinterpret_cast<const float4*>(g_a + c);
    float4 xm = *reinterpret_cast<const float4*>(g_xmean + c);

    float4 v;
    v.x = w.x + om * ga.x - gb * xm.x;
    v.y = w.y + om * ga.y - gb * xm.y;
    v.z = w.z + om * ga.z - gb * xm.z;
    v.w = w.w + om * ga.w - gb * xm.w;
#define CLIP1(t) t = fminf(fmaxf(t, -1.0f), 1.0f)
    CLIP1(v.x); CLIP1(v.y); CLIP1(v.z); CLIP1(v.w);
    v.x *= factor; v.y *= factor; v.z *= factor; v.w *= factor;
    CLIP1(v.x); CLIP1(v.y); CLIP1(v.z); CLIP1(v.w);
#undef CLIP1
    *reinterpret_cast<float4*>(out_w + base) = v;

    if (i4 < H_DIM) {
        float mlr = *d_mlr;
        float mv = meta[i4] + mlr * (g_omean[i4] - meta[i4]);
        out_meta[i4] = fminf(fmaxf(mv, 0.0f), 2.0f);
    }
}

// ---------------------------------------------------------------------------
extern "C" void kernel_launch(void* const* d_in, const int* in_sizes, int n_in,
                              void* d_out, int out_size)
{
    const float* x      = (const float*)d_in[0];
    const float* W      = (const float*)d_in[1];
    const float* meta   = (const float*)d_in[2];
    const float* pre    = (const float*)d_in[3];
    const float* post   = (const float*)d_in[4];
    const float* act    = (const float*)d_in[5];
    const int*   ptr    = (const int*)d_in[6];
    const float* win    = (const float*)d_in[7];
    const float* dec    = (const float*)d_in[8];
    const float* target = (const float*)d_in[9];
    const float* hrate  = (const float*)d_in[10];
    const float* mlr    = (const float*)d_in[11];

    const int H = H_DIM;
    const int B = in_sizes[0] / H;       // 16384
    const int ACT = in_sizes[5];         // 1000

    float* out      = (float*)d_out;
    float* out_w    = out + (size_t)B * H;
    float* out_meta = out_w + (size_t)H * H;
    float* out_hist = out_meta + H;

    const float invB = 1.0f / (float)B;

    static bool attr_done = false;
    if (!attr_done) {
        cudaFuncSetAttribute(gemm_mma, cudaFuncAttributeMaxDynamicSharedMemorySize,
                             GEMM_SMEM);
        attr_done = true;
    }

    // 1) x conversion + partials, W scale+transpose (one launch)
    convert_fused<<<dim3(1, SPLITX + 1024), 256>>>(x, W, meta);

    // 2) GEMM (+ fused output column partials)
    dim3 ggrid(H / TN, B / TM);
    gemm_mma<<<ggrid, 256, GEMM_SMEM>>>(out);

    // 3) xmean + omean + STDP
    reduce_o_stdp<<<H / 256, 256>>>(pre, post, win, dec, invB);

    // 4) scalars + hist
    scalars_kernel<<<1, 256>>>(act, ptr, target, hrate, out_hist, ACT);

    // 5) weights + meta
    weights_meta_kernel<<<(H * H) / 1024, 256>>>(W, meta, mlr, out_w, out_meta);
}

// round 8
// speedup vs baseline: 1.0915x; 1.0444x over previous
#include <cuda_runtime.h>
#include <cuda_fp16.h>
#include <cstdint>

// ---------------------------------------------------------------------------
// SynapticPlasticityModule on GB300 — mma.sync fp16 GEMM (round-4 config,
// untouched) + minimal launch count (5 kernels).
// Outputs (d_out, fp32): [output B*H][new_w H*H][new_meta H][hist ACT]
// ---------------------------------------------------------------------------

#define H_DIM 1024
#define B_DIM 16384
#define HIST_LEN 100
#define SPLITX 256
#define MTILES (B_DIM / 128)

#define TM 128
#define TN 128
#define KC 64
#define NCHUNK (H_DIM / KC)                 // 16
#define STAGE_BYTES (TM * 128 + TN * 128)   // 32768
#define GEMM_SMEM (2 * STAGE_BYTES)         // 65536

// __device__ scratch (allocation-free rule: static module storage)
__device__ __half g_xh[(size_t)B_DIM * H_DIM];
__device__ __half g_wh[(size_t)H_DIM * H_DIM];
__device__ float  g_xpart[SPLITX * H_DIM];
__device__ float  g_opart[MTILES * H_DIM];
__device__ float  g_xmean[H_DIM];
__device__ float  g_omean[H_DIM];
__device__ float  g_a[H_DIM];
__device__ float  g_b[H_DIM];

__device__ __forceinline__ uint32_t smem_u32(const void* p) {
    uint32_t a;
    asm("{ .reg .u64 t; cvta.to.shared.u64 t, %1; cvt.u32.u64 %0, t; }"
        : "=r"(a) : "l"(p));
    return a;
}
#define SW128(off) ((off) ^ (((off) >> 3) & 0x70))

#define CP_ASYNC16(smem_addr, gptr) \
    asm volatile("cp.async.cg.shared.global [%0], [%1], 16;" \
                 :: "r"(smem_addr), "l"(gptr) : "memory")
#define CP_COMMIT() asm volatile("cp.async.commit_group;" ::: "memory")
#define CP_WAIT1()  asm volatile("cp.async.wait_group 1;" ::: "memory")
#define CP_WAIT0()  asm volatile("cp.async.wait_group 0;" ::: "memory")

__device__ __forceinline__ void ldmx4(uint32_t* r, uint32_t addr) {
    asm volatile("ldmatrix.sync.aligned.m8n8.x4.shared.b16 {%0,%1,%2,%3}, [%4];"
                 : "=r"(r[0]), "=r"(r[1]), "=r"(r[2]), "=r"(r[3]) : "r"(addr));
}
__device__ __forceinline__ void mma16816(float* d, const uint32_t* a,
                                         const uint32_t* b) {
    asm volatile(
        "mma.sync.aligned.m16n8k16.row.col.f32.f16.f16.f32 "
        "{%0,%1,%2,%3}, {%4,%5,%6,%7}, {%8,%9}, {%0,%1,%2,%3};"
        : "+f"(d[0]), "+f"(d[1]), "+f"(d[2]), "+f"(d[3])
        : "r"(a[0]), "r"(a[1]), "r"(a[2]), "r"(a[3]), "r"(b[0]), "r"(b[1]));
}

// ---------------------------------------------------------------------------
// convert_x: fp32 -> fp16 (float4 path), fused column partial sums. (r4 exact)
// ---------------------------------------------------------------------------
__global__ __launch_bounds__(256) void convert_x(const float* __restrict__ x)
{
    const int rows_per = B_DIM / SPLITX;     // 64
    const int c4 = threadIdx.x * 4;
    const size_t row0 = (size_t)blockIdx.y * rows_per;

    float4 s = make_float4(0.f, 0.f, 0.f, 0.f);
    const float* p = x + row0 * H_DIM + c4;
    __half* q = g_xh + row0 * H_DIM + c4;

#pragma unroll 4
    for (int r = 0; r < rows_per; r++) {
        float4 v = *reinterpret_cast<const float4*>(p + (size_t)r * H_DIM);
        s.x += v.x; s.y += v.y; s.z += v.z; s.w += v.w;
        __half2 h01 = __floats2half2_rn(v.x, v.y);
        __half2 h23 = __floats2half2_rn(v.z, v.w);
        *reinterpret_cast<uint2*>(q + (size_t)r * H_DIM) =
            make_uint2(*reinterpret_cast<uint32_t*>(&h01),
                       *reinterpret_cast<uint32_t*>(&h23));
    }
    *reinterpret_cast<float4*>(g_xpart + blockIdx.y * H_DIM + c4) = s;
}

// convert_w: (W[k][n]*meta[n]) -> g_wh[n][k] fp16 (transposed). (r4 exact)
__global__ void convert_w(const float* __restrict__ W, const float* __restrict__ meta)
{
    __shared__ float tile[32][33];
    int n0 = blockIdx.x * 32, k0 = blockIdx.y * 32;
    int tx = threadIdx.x, ty = threadIdx.y;
#pragma unroll
    for (int i = ty; i < 32; i += 8)
        tile[i][tx] = W[(size_t)(k0 + i) * H_DIM + n0 + tx] * meta[n0 + tx];
    __syncthreads();
#pragma unroll
    for (int i = ty; i < 32; i += 8)
        g_wh[(size_t)(n0 + i) * H_DIM + k0 + tx] = __float2half_rn(tile[tx][i]);
}

// ---------------------------------------------------------------------------
// GEMM (r4 exact): 128x128 CTA, 8 warps of 32x64, 2-stage cp.async,
// fused column-sum epilogue.
// ---------------------------------------------------------------------------
__global__ __launch_bounds__(256) void gemm_mma(float* __restrict__ C)
{
    extern __shared__ char smem[];
    const uint32_t sb = smem_u32(smem);
    const int tid  = threadIdx.x;
    const int wid  = tid >> 5;
    const int lane = tid & 31;
    const int m0 = blockIdx.y * TM;
    const int n0 = blockIdx.x * TN;
    const int m_w = (wid & 3) * 32;
    const int n_w = (wid >> 2) * 64;

    float acc[2][8][4];
#pragma unroll
    for (int i = 0; i < 2; i++)
#pragma unroll
        for (int j = 0; j < 8; j++)
#pragma unroll
            for (int q = 0; q < 4; q++) acc[i][j][q] = 0.0f;

    const int lrow = tid >> 3;
    const int lseg = tid & 7;
    const __half* gA = g_xh + (size_t)(m0 + lrow) * H_DIM + lseg * 8;
    const __half* gB = g_wh + (size_t)(n0 + lrow) * H_DIM + lseg * 8;

#define LOAD_STAGE(c, s) do {                                                  \
    const uint32_t base = sb + (s) * STAGE_BYTES;                              \
    const int koff = (c) * KC;                                                 \
    _Pragma("unroll")                                                          \
    for (int it = 0; it < 4; it++) {                                           \
        int row = it * 32 + lrow;                                              \
        uint32_t off = SW128((uint32_t)(row * 128 + lseg * 16));               \
        CP_ASYNC16(base + off, gA + (size_t)it * 32 * H_DIM + koff);           \
    }                                                                          \
    _Pragma("unroll")                                                          \
    for (int it = 0; it < 4; it++) {                                           \
        int row = it * 32 + lrow;                                              \
        uint32_t off = SW128((uint32_t)(row * 128 + lseg * 16));               \
        CP_ASYNC16(base + TM * 128 + off, gB + (size_t)it * 32 * H_DIM + koff);\
    }                                                                          \
} while (0)

    LOAD_STAGE(0, 0);
    CP_COMMIT();

    const int a_row = m_w + (lane & 15);
    const int a_colb = (lane >> 4) << 4;
    const int b_row = n_w + (lane & 7) + ((lane >> 4) & 1) * 8;
    const int b_colb = ((lane >> 3) & 1) << 4;

    for (int c = 0; c < NCHUNK; c++) {
        if (c + 1 < NCHUNK) {
            LOAD_STAGE(c + 1, (c + 1) & 1);
            CP_COMMIT();
            CP_WAIT1();
        } else {
            CP_WAIT0();
        }
        __syncthreads();

        const uint32_t baseA = sb + (c & 1) * STAGE_BYTES;
        const uint32_t baseB = baseA + TM * 128;

#pragma unroll
        for (int ks = 0; ks < KC / 16; ks++) {
            uint32_t a[2][4], b[4][4];
#pragma unroll
            for (int mi = 0; mi < 2; mi++) {
                uint32_t off = (uint32_t)((a_row + mi * 16) * 128 + ks * 32 + a_colb);
                ldmx4(a[mi], baseA + SW128(off));
            }
#pragma unroll
            for (int bq = 0; bq < 4; bq++) {
                uint32_t off = (uint32_t)((b_row + bq * 16) * 128 + ks * 32 + b_colb);
                ldmx4(b[bq], baseB + SW128(off));
            }
#pragma unroll
            for (int mi = 0; mi < 2; mi++)
#pragma unroll
                for (int bq = 0; bq < 4; bq++) {
                    mma16816(acc[mi][bq * 2 + 0], a[mi], &b[bq][0]);
                    mma16816(acc[mi][bq * 2 + 1], a[mi], &b[bq][2]);
                }
        }
        __syncthreads();
    }

    // ---- epilogue 1: store C tile
    const int g = lane >> 2, tig = lane & 3;
#pragma unroll
    for (int mi = 0; mi < 2; mi++) {
        const size_t r0 = (size_t)(m0 + m_w + mi * 16 + g);
#pragma unroll
        for (int ni = 0; ni < 8; ni++) {
            const int col = n0 + n_w + ni * 8 + tig * 2;
            *reinterpret_cast<float2*>(C + r0 * H_DIM + col) =
                make_float2(acc[mi][ni][0], acc[mi][ni][1]);
            *reinterpret_cast<float2*>(C + (r0 + 8) * H_DIM + col) =
                make_float2(acc[mi][ni][2], acc[mi][ni][3]);
        }
    }

    // ---- epilogue 2: fused column sums -> g_opart[blockIdx.y]
    float* red = reinterpret_cast<float*>(smem);
#pragma unroll
    for (int ni = 0; ni < 8; ni++) {
        float s0 = acc[0][ni][0] + acc[0][ni][2] + acc[1][ni][0] + acc[1][ni][2];
        float s1 = acc[0][ni][1] + acc[0][ni][3] + acc[1][ni][1] + acc[1][ni][3];
#pragma unroll
        for (int o = 4; o < 32; o <<= 1) {
            s0 += __shfl_xor_sync(0xffffffffu, s0, o);
            s1 += __shfl_xor_sync(0xffffffffu, s1, o);
        }
        if (lane < 4) {
            int col = n_w + ni * 8 + lane * 2;
            red[(wid & 3) * 128 + col]     = s0;
            red[(wid & 3) * 128 + col + 1] = s1;
        }
    }
    __syncthreads();
    if (tid < 128) {
        float s = red[tid] + red[128 + tid] + red[256 + tid] + red[384 + tid];
        g_opart[(size_t)blockIdx.y * H_DIM + n0 + tid] = s;
    }
#undef LOAD_STAGE
}

// ---------------------------------------------------------------------------
// reduce xmean + omean + STDP weighted history sums.  grid H/256.
// ---------------------------------------------------------------------------
__global__ __launch_bounds__(256) void reduce_o_stdp(
    const float* __restrict__ pre_hist, const float* __restrict__ post_hist,
    const float* __restrict__ d_win, const float* __restrict__ d_dec, float invB)
{
    int h = blockIdx.x * 256 + threadIdx.x;

    float sx = 0.0f;
    for (int i = 0; i < SPLITX; i++) sx += g_xpart[i * H_DIM + h];
    g_xmean[h] = sx * invB;

    float s = 0.0f;
    for (int i = 0; i < MTILES; i++) s += g_opart[i * H_DIM + h];
    float om = s * invB;
    g_omean[h] = om;

    float win = *d_win, dec = *d_dec;
    float a = 0.0f, b = 0.0f;
    for (int i = 0; i < 99; i++) {
        float dt = (float)(HIST_LEN - i) * win;
        float wv = 0.01f * expf(-dt * dec);
        a += wv * pre_hist[(i + 1) * H_DIM + h];
        if (i >= 1) b += wv * post_hist[(i + 1) * H_DIM + h];
    }
    float w99 = 0.01f * expf(-(1.0f * win) * dec);
    b += w99 * om;
    g_a[h] = a;
    g_b[h] = b;
}

// ---------------------------------------------------------------------------
// weights + meta + scalars + hist, one kernel. Every block redundantly
// computes m (overall output mean) and the homeostatic factor — identical
// summation order per block => bit-deterministic across blocks.
// grid = H*H/1024, block 256, each thread one float4.
// ---------------------------------------------------------------------------
__global__ __launch_bounds__(256) void weights_meta_kernel(
    const float* __restrict__ W, const float* __restrict__ meta,
    const float* __restrict__ act, const int* __restrict__ d_ptr,
    const float* __restrict__ d_target, const float* __restrict__ d_hrate,
    const float* __restrict__ d_mlr,
    float* __restrict__ out_w, float* __restrict__ out_meta,
    float* __restrict__ out_hist, int act_len)
{
    __shared__ float sred[8];
    __shared__ float sbc[2];
    const int tid = threadIdx.x;
    const int wid = tid >> 5;
    const int lane = tid & 31;

    // ---- redundant scalars: m = mean(g_omean), act_sum = sum(act)
    float pm = 0.0f;
#pragma unroll
    for (int i = tid; i < H_DIM; i += 256) pm += g_omean[i];
#pragma unroll
    for (int o = 16; o > 0; o >>= 1) pm += __shfl_xor_sync(0xffffffffu, pm, o);
    if (lane == 0) sred[wid] = pm;
    __syncthreads();
    if (wid == 0) {
        float t = (lane < 8) ? sred[lane] : 0.0f;
#pragma unroll
        for (int o = 4; o > 0; o >>= 1) t += __shfl_xor_sync(0xffffffffu, t, o);
        if (lane == 0) sbc[0] = t / (float)H_DIM;
    }
    __syncthreads();

    float pa = 0.0f;
    for (int i = tid; i < act_len; i += 256) pa += act[i];
#pragma unroll
    for (int o = 16; o > 0; o >>= 1) pa += __shfl_xor_sync(0xffffffffu, pa, o);
    if (lane == 0) sred[wid] = pa;
    __syncthreads();
    if (wid == 0) {
        float t = (lane < 8) ? sred[lane] : 0.0f;
#pragma unroll
        for (int o = 4; o > 0; o >>= 1) t += __shfl_xor_sync(0xffffffffu, t, o);
        if (lane == 0) sbc[1] = t;
    }
    __syncthreads();

    const float m = sbc[0];
    const int ptr = *d_ptr;
    const float hist_mean = (sbc[1] - act[ptr] + m) / (float)act_len;
    const float factor = 1.0f + (*d_hrate) * ((*d_target) - hist_mean);

    // ---- block 0 writes hist output
    if (blockIdx.x == 0) {
        for (int i = tid; i < act_len; i += 256)
            out_hist[i] = (i == ptr) ? m : act[i];
    }

    // ---- weight update (float4)
    size_t i4 = (size_t)blockIdx.x * 256 + tid;
    size_t base = i4 * 4;
    int r = (int)(base >> 10);
    int c = (int)(base & (H_DIM - 1));
    float om = g_omean[r], gb = g_b[r];

    float4 w  = *reinterpret_cast<const float4*>(W + base);
    float4 ga = *reinterpret_cast<const float4*>(g_a + c);
    float4 xm = *reinterpret_cast<const float4*>(g_xmean + c);

    float4 v;
    v.x = w.x + om * ga.x - gb * xm.x;
    v.y = w.y + om * ga.y - gb * xm.y;
    v.z = w.z + om * ga.z - gb * xm.z;
    v.w = w.w + om * ga.w - gb * xm.w;
#define CLIP1(t) t = fminf(fmaxf(t, -1.0f), 1.0f)
    CLIP1(v.x); CLIP1(v.y); CLIP1(v.z); CLIP1(v.w);
    v.x *= factor; v.y *= factor; v.z *= factor; v.w *= factor;
    CLIP1(v.x); CLIP1(v.y); CLIP1(v.z); CLIP1(v.w);
#undef CLIP1
    *reinterpret_cast<float4*>(out_w + base) = v;

    // ---- meta update (first H threads overall)
    if (i4 < H_DIM) {
        float mlr = *d_mlr;
        float mv = meta[i4] + mlr * (g_omean[i4] - meta[i4]);
        out_meta[i4] = fminf(fmaxf(mv, 0.0f), 2.0f);
    }
}

// ---------------------------------------------------------------------------
extern "C" void kernel_launch(void* const* d_in, const int* in_sizes, int n_in,
                              void* d_out, int out_size)
{
    const float* x      = (const float*)d_in[0];
    const float* W      = (const float*)d_in[1];
    const float* meta   = (const float*)d_in[2];
    const float* pre    = (const float*)d_in[3];
    const float* post   = (const float*)d_in[4];
    const float* act    = (const float*)d_in[5];
    const int*   ptr    = (const int*)d_in[6];
    const float* win    = (const float*)d_in[7];
    const float* dec    = (const float*)d_in[8];
    const float* target = (const float*)d_in[9];
    const float* hrate  = (const float*)d_in[10];
    const float* mlr    = (const float*)d_in[11];

    const int H = H_DIM;
    const int B = in_sizes[0] / H;       // 16384
    const int ACT = in_sizes[5];         // 1000

    float* out      = (float*)d_out;
    float* out_w    = out + (size_t)B * H;
    float* out_meta = out_w + (size_t)H * H;
    float* out_hist = out_meta + H;

    const float invB = 1.0f / (float)B;

    static bool attr_done = false;
    if (!attr_done) {
        cudaFuncSetAttribute(gemm_mma, cudaFuncAttributeMaxDynamicSharedMemorySize,
                             GEMM_SMEM);
        attr_done = true;
    }

    // 1) x conversion + partials  (r4 exact)
    convert_x<<<dim3(1, SPLITX), 256>>>(x);
    // 2) W scale + transpose      (r4 exact)
    convert_w<<<dim3(32, 32), dim3(32, 8)>>>(W, meta);
    // 3) GEMM (+ fused output column partials)
    dim3 ggrid(H / TN, B / TM);
    gemm_mma<<<ggrid, 256, GEMM_SMEM>>>(out);
    // 4) xmean + omean + STDP
    reduce_o_stdp<<<H / 256, 256>>>(pre, post, win, dec, invB);
    // 5) weights + meta + scalars + hist
    weights_meta_kernel<<<(H * H) / 1024, 256>>>(
        W, meta, act, ptr, target, hrate, mlr, out_w, out_meta, out_hist, ACT);
}

// round 9
// speedup vs baseline: 1.3209x; 1.2101x over previous
#include <cuda_runtime.h>
#include <cuda_fp16.h>
#include <cstdint>

// ---------------------------------------------------------------------------
// SynapticPlasticityModule on GB300 — mma.sync fp16 GEMM (round-4 config,
// untouched) + warp-per-column reductions + fused tail.
// Outputs (d_out, fp32): [output B*H][new_w H*H][new_meta H][hist ACT]
// ---------------------------------------------------------------------------

#define H_DIM 1024
#define B_DIM 16384
#define HIST_LEN 100
#define SPLITX 256
#define MTILES (B_DIM / 128)

#define TM 128
#define TN 128
#define KC 64
#define NCHUNK (H_DIM / KC)                 // 16
#define STAGE_BYTES (TM * 128 + TN * 128)   // 32768
#define GEMM_SMEM (2 * STAGE_BYTES)         // 65536

// __device__ scratch (allocation-free rule: static module storage)
__device__ __half g_xh[(size_t)B_DIM * H_DIM];
__device__ __half g_wh[(size_t)H_DIM * H_DIM];
__device__ float  g_xpart[SPLITX * H_DIM];
__device__ float  g_opart[MTILES * H_DIM];
__device__ float  g_xmean[H_DIM];
__device__ float  g_omean[H_DIM];
__device__ float  g_a[H_DIM];
__device__ float  g_b[H_DIM];

__device__ __forceinline__ uint32_t smem_u32(const void* p) {
    uint32_t a;
    asm("{ .reg .u64 t; cvta.to.shared.u64 t, %1; cvt.u32.u64 %0, t; }"
        : "=r"(a) : "l"(p));
    return a;
}
#define SW128(off) ((off) ^ (((off) >> 3) & 0x70))

#define CP_ASYNC16(smem_addr, gptr) \
    asm volatile("cp.async.cg.shared.global [%0], [%1], 16;" \
                 :: "r"(smem_addr), "l"(gptr) : "memory")
#define CP_COMMIT() asm volatile("cp.async.commit_group;" ::: "memory")
#define CP_WAIT1()  asm volatile("cp.async.wait_group 1;" ::: "memory")
#define CP_WAIT0()  asm volatile("cp.async.wait_group 0;" ::: "memory")

__device__ __forceinline__ void ldmx4(uint32_t* r, uint32_t addr) {
    asm volatile("ldmatrix.sync.aligned.m8n8.x4.shared.b16 {%0,%1,%2,%3}, [%4];"
                 : "=r"(r[0]), "=r"(r[1]), "=r"(r[2]), "=r"(r[3]) : "r"(addr));
}
__device__ __forceinline__ void mma16816(float* d, const uint32_t* a,
                                         const uint32_t* b) {
    asm volatile(
        "mma.sync.aligned.m16n8k16.row.col.f32.f16.f16.f32 "
        "{%0,%1,%2,%3}, {%4,%5,%6,%7}, {%8,%9}, {%0,%1,%2,%3};"
        : "+f"(d[0]), "+f"(d[1]), "+f"(d[2]), "+f"(d[3])
        : "r"(a[0]), "r"(a[1]), "r"(a[2]), "r"(a[3]), "r"(b[0]), "r"(b[1]));
}

// ---------------------------------------------------------------------------
// convert_x: fp32 -> fp16 (float4 path), fused column partial sums. (r4 exact)
// ---------------------------------------------------------------------------
__global__ __launch_bounds__(256) void convert_x(const float* __restrict__ x)
{
    const int rows_per = B_DIM / SPLITX;     // 64
    const int c4 = threadIdx.x * 4;
    const size_t row0 = (size_t)blockIdx.y * rows_per;

    float4 s = make_float4(0.f, 0.f, 0.f, 0.f);
    const float* p = x + row0 * H_DIM + c4;
    __half* q = g_xh + row0 * H_DIM + c4;

#pragma unroll 4
    for (int r = 0; r < rows_per; r++) {
        float4 v = *reinterpret_cast<const float4*>(p + (size_t)r * H_DIM);
        s.x += v.x; s.y += v.y; s.z += v.z; s.w += v.w;
        __half2 h01 = __floats2half2_rn(v.x, v.y);
        __half2 h23 = __floats2half2_rn(v.z, v.w);
        *reinterpret_cast<uint2*>(q + (size_t)r * H_DIM) =
            make_uint2(*reinterpret_cast<uint32_t*>(&h01),
                       *reinterpret_cast<uint32_t*>(&h23));
    }
    *reinterpret_cast<float4*>(g_xpart + blockIdx.y * H_DIM + c4) = s;
}

// convert_w: (W[k][n]*meta[n]) -> g_wh[n][k] fp16 (transposed). (r4 exact)
__global__ void convert_w(const float* __restrict__ W, const float* __restrict__ meta)
{
    __shared__ float tile[32][33];
    int n0 = blockIdx.x * 32, k0 = blockIdx.y * 32;
    int tx = threadIdx.x, ty = threadIdx.y;
#pragma unroll
    for (int i = ty; i < 32; i += 8)
        tile[i][tx] = W[(size_t)(k0 + i) * H_DIM + n0 + tx] * meta[n0 + tx];
    __syncthreads();
#pragma unroll
    for (int i = ty; i < 32; i += 8)
        g_wh[(size_t)(n0 + i) * H_DIM + k0 + tx] = __float2half_rn(tile[tx][i]);
}

// ---------------------------------------------------------------------------
// GEMM (r4 exact): 128x128 CTA, 8 warps of 32x64, 2-stage cp.async,
// fused column-sum epilogue.
// ---------------------------------------------------------------------------
__global__ __launch_bounds__(256) void gemm_mma(float* __restrict__ C)
{
    extern __shared__ char smem[];
    const uint32_t sb = smem_u32(smem);
    const int tid  = threadIdx.x;
    const int wid  = tid >> 5;
    const int lane = tid & 31;
    const int m0 = blockIdx.y * TM;
    const int n0 = blockIdx.x * TN;
    const int m_w = (wid & 3) * 32;
    const int n_w = (wid >> 2) * 64;

    float acc[2][8][4];
#pragma unroll
    for (int i = 0; i < 2; i++)
#pragma unroll
        for (int j = 0; j < 8; j++)
#pragma unroll
            for (int q = 0; q < 4; q++) acc[i][j][q] = 0.0f;

    const int lrow = tid >> 3;
    const int lseg = tid & 7;
    const __half* gA = g_xh + (size_t)(m0 + lrow) * H_DIM + lseg * 8;
    const __half* gB = g_wh + (size_t)(n0 + lrow) * H_DIM + lseg * 8;

#define LOAD_STAGE(c, s) do {                                                  \
    const uint32_t base = sb + (s) * STAGE_BYTES;                              \
    const int koff = (c) * KC;                                                 \
    _Pragma("unroll")                                                          \
    for (int it = 0; it < 4; it++) {                                           \
        int row = it * 32 + lrow;                                              \
        uint32_t off = SW128((uint32_t)(row * 128 + lseg * 16));               \
        CP_ASYNC16(base + off, gA + (size_t)it * 32 * H_DIM + koff);           \
    }                                                                          \
    _Pragma("unroll")                                                          \
    for (int it = 0; it < 4; it++) {                                           \
        int row = it * 32 + lrow;                                              \
        uint32_t off = SW128((uint32_t)(row * 128 + lseg * 16));               \
        CP_ASYNC16(base + TM * 128 + off, gB + (size_t)it * 32 * H_DIM + koff);\
    }                                                                          \
} while (0)

    LOAD_STAGE(0, 0);
    CP_COMMIT();

    const int a_row = m_w + (lane & 15);
    const int a_colb = (lane >> 4) << 4;
    const int b_row = n_w + (lane & 7) + ((lane >> 4) & 1) * 8;
    const int b_colb = ((lane >> 3) & 1) << 4;

    for (int c = 0; c < NCHUNK; c++) {
        if (c + 1 < NCHUNK) {
            LOAD_STAGE(c + 1, (c + 1) & 1);
            CP_COMMIT();
            CP_WAIT1();
        } else {
            CP_WAIT0();
        }
        __syncthreads();

        const uint32_t baseA = sb + (c & 1) * STAGE_BYTES;
        const uint32_t baseB = baseA + TM * 128;

#pragma unroll
        for (int ks = 0; ks < KC / 16; ks++) {
            uint32_t a[2][4], b[4][4];
#pragma unroll
            for (int mi = 0; mi < 2; mi++) {
                uint32_t off = (uint32_t)((a_row + mi * 16) * 128 + ks * 32 + a_colb);
                ldmx4(a[mi], baseA + SW128(off));
            }
#pragma unroll
            for (int bq = 0; bq < 4; bq++) {
                uint32_t off = (uint32_t)((b_row + bq * 16) * 128 + ks * 32 + b_colb);
                ldmx4(b[bq], baseB + SW128(off));
            }
#pragma unroll
            for (int mi = 0; mi < 2; mi++)
#pragma unroll
                for (int bq = 0; bq < 4; bq++) {
                    mma16816(acc[mi][bq * 2 + 0], a[mi], &b[bq][0]);
                    mma16816(acc[mi][bq * 2 + 1], a[mi], &b[bq][2]);
                }
        }
        __syncthreads();
    }

    // ---- epilogue 1: store C tile
    const int g = lane >> 2, tig = lane & 3;
#pragma unroll
    for (int mi = 0; mi < 2; mi++) {
        const size_t r0 = (size_t)(m0 + m_w + mi * 16 + g);
#pragma unroll
        for (int ni = 0; ni < 8; ni++) {
            const int col = n0 + n_w + ni * 8 + tig * 2;
            *reinterpret_cast<float2*>(C + r0 * H_DIM + col) =
                make_float2(acc[mi][ni][0], acc[mi][ni][1]);
            *reinterpret_cast<float2*>(C + (r0 + 8) * H_DIM + col) =
                make_float2(acc[mi][ni][2], acc[mi][ni][3]);
        }
    }

    // ---- epilogue 2: fused column sums -> g_opart[blockIdx.y]
    float* red = reinterpret_cast<float*>(smem);
#pragma unroll
    for (int ni = 0; ni < 8; ni++) {
        float s0 = acc[0][ni][0] + acc[0][ni][2] + acc[1][ni][0] + acc[1][ni][2];
        float s1 = acc[0][ni][1] + acc[0][ni][3] + acc[1][ni][1] + acc[1][ni][3];
#pragma unroll
        for (int o = 4; o < 32; o <<= 1) {
            s0 += __shfl_xor_sync(0xffffffffu, s0, o);
            s1 += __shfl_xor_sync(0xffffffffu, s1, o);
        }
        if (lane < 4) {
            int col = n_w + ni * 8 + lane * 2;
            red[(wid & 3) * 128 + col]     = s0;
            red[(wid & 3) * 128 + col + 1] = s1;
        }
    }
    __syncthreads();
    if (tid < 128) {
        float s = red[tid] + red[128 + tid] + red[256 + tid] + red[384 + tid];
        g_opart[(size_t)blockIdx.y * H_DIM + n0 + tid] = s;
    }
#undef LOAD_STAGE
}

// ---------------------------------------------------------------------------
// Warp-per-h reduction: xmean + omean + STDP sums. grid 128, block 256.
// Warp handles one h; lanes split the i dimension, shfl-tree combine.
// ---------------------------------------------------------------------------
__global__ __launch_bounds__(256) void reduce_o_stdp(
    const float* __restrict__ pre_hist, const float* __restrict__ post_hist,
    const float* __restrict__ d_win, const float* __restrict__ d_dec, float invB)
{
    const int wid  = threadIdx.x >> 5;
    const int lane = threadIdx.x & 31;
    const int h = blockIdx.x * 8 + wid;

    const float win = *d_win, dec = *d_dec;

    float sx = 0.0f;
#pragma unroll
    for (int i = 0; i < SPLITX; i += 32)
        sx += g_xpart[(size_t)(i + lane) * H_DIM + h];

    float so = 0.0f;
#pragma unroll
    for (int i = 0; i < MTILES; i += 32)
        so += g_opart[(size_t)(i + lane) * H_DIM + h];

    float a = 0.0f, b = 0.0f;
#pragma unroll
    for (int ii = 0; ii < 4; ii++) {
        int i = ii * 32 + lane;
        if (i < 99) {
            float dt = (float)(HIST_LEN - i) * win;
            float wv = 0.01f * expf(-dt * dec);
            a += wv * pre_hist[(size_t)(i + 1) * H_DIM + h];
            if (i >= 1) b += wv * post_hist[(size_t)(i + 1) * H_DIM + h];
        }
    }

#pragma unroll
    for (int o = 16; o > 0; o >>= 1) {
        sx += __shfl_xor_sync(0xffffffffu, sx, o);
        so += __shfl_xor_sync(0xffffffffu, so, o);
        a  += __shfl_xor_sync(0xffffffffu, a,  o);
        b  += __shfl_xor_sync(0xffffffffu, b,  o);
    }

    if (lane == 0) {
        g_xmean[h] = sx * invB;
        float om = so * invB;
        g_omean[h] = om;
        g_a[h] = a;
        float w99 = 0.01f * expf(-(1.0f * win) * dec);
        g_b[h] = b + w99 * om;
    }
}

// ---------------------------------------------------------------------------
// weights + meta + scalars + hist, one kernel (r8).
// ---------------------------------------------------------------------------
__global__ __launch_bounds__(256) void weights_meta_kernel(
    const float* __restrict__ W, const float* __restrict__ meta,
    const float* __restrict__ act, const int* __restrict__ d_ptr,
    const float* __restrict__ d_target, const float* __restrict__ d_hrate,
    const float* __restrict__ d_mlr,
    float* __restrict__ out_w, float* __restrict__ out_meta,
    float* __restrict__ out_hist, int act_len)
{
    __shared__ float sred[8];
    __shared__ float sbc[2];
    const int tid = threadIdx.x;
    const int wid = tid >> 5;
    const int lane = tid & 31;

    float pm = 0.0f;
#pragma unroll
    for (int i = tid; i < H_DIM; i += 256) pm += g_omean[i];
#pragma unroll
    for (int o = 16; o > 0; o >>= 1) pm += __shfl_xor_sync(0xffffffffu, pm, o);
    if (lane == 0) sred[wid] = pm;
    __syncthreads();
    if (wid == 0) {
        float t = (lane < 8) ? sred[lane] : 0.0f;
#pragma unroll
        for (int o = 4; o > 0; o >>= 1) t += __shfl_xor_sync(0xffffffffu, t, o);
        if (lane == 0) sbc[0] = t / (float)H_DIM;
    }
    __syncthreads();

    float pa = 0.0f;
    for (int i = tid; i < act_len; i += 256) pa += act[i];
#pragma unroll
    for (int o = 16; o > 0; o >>= 1) pa += __shfl_xor_sync(0xffffffffu, pa, o);
    if (lane == 0) sred[wid] = pa;
    __syncthreads();
    if (wid == 0) {
        float t = (lane < 8) ? sred[lane] : 0.0f;
#pragma unroll
        for (int o = 4; o > 0; o >>= 1) t += __shfl_xor_sync(0xffffffffu, t, o);
        if (lane == 0) sbc[1] = t;
    }
    __syncthreads();

    const float m = sbc[0];
    const int ptr = *d_ptr;
    const float hist_mean = (sbc[1] - act[ptr] + m) / (float)act_len;
    const float factor = 1.0f + (*d_hrate) * ((*d_target) - hist_mean);

    if (blockIdx.x == 0) {
        for (int i = tid; i < act_len; i += 256)
            out_hist[i] = (i == ptr) ? m : act[i];
    }

    size_t i4 = (size_t)blockIdx.x * 256 + tid;
    size_t base = i4 * 4;
    int r = (int)(base >> 10);
    int c = (int)(base & (H_DIM - 1));
    float om = g_omean[r], gb = g_b[r];

    float4 w  = *reinterpret_cast<const float4*>(W + base);
    float4 ga = *reinterpret_cast<const float4*>(g_a + c);
    float4 xm = *reinterpret_cast<const float4*>(g_xmean + c);

    float4 v;
    v.x = w.x + om * ga.x - gb * xm.x;
    v.y = w.y + om * ga.y - gb * xm.y;
    v.z = w.z + om * ga.z - gb * xm.z;
    v.w = w.w + om * ga.w - gb * xm.w;
#define CLIP1(t) t = fminf(fmaxf(t, -1.0f), 1.0f)
    CLIP1(v.x); CLIP1(v.y); CLIP1(v.z); CLIP1(v.w);
    v.x *= factor; v.y *= factor; v.z *= factor; v.w *= factor;
    CLIP1(v.x); CLIP1(v.y); CLIP1(v.z); CLIP1(v.w);
#undef CLIP1
    *reinterpret_cast<float4*>(out_w + base) = v;

    if (i4 < H_DIM) {
        float mlr = *d_mlr;
        float mv = meta[i4] + mlr * (g_omean[i4] - meta[i4]);
        out_meta[i4] = fminf(fmaxf(mv, 0.0f), 2.0f);
    }
}

// ---------------------------------------------------------------------------
extern "C" void kernel_launch(void* const* d_in, const int* in_sizes, int n_in,
                              void* d_out, int out_size)
{
    const float* x      = (const float*)d_in[0];
    const float* W      = (const float*)d_in[1];
    const float* meta   = (const float*)d_in[2];
    const float* pre    = (const float*)d_in[3];
    const float* post   = (const float*)d_in[4];
    const float* act    = (const float*)d_in[5];
    const int*   ptr    = (const int*)d_in[6];
    const float* win    = (const float*)d_in[7];
    const float* dec    = (const float*)d_in[8];
    const float* target = (const float*)d_in[9];
    const float* hrate  = (const float*)d_in[10];
    const float* mlr    = (const float*)d_in[11];

    const int H = H_DIM;
    const int B = in_sizes[0] / H;       // 16384
    const int ACT = in_sizes[5];         // 1000

    float* out      = (float*)d_out;
    float* out_w    = out + (size_t)B * H;
    float* out_meta = out_w + (size_t)H * H;
    float* out_hist = out_meta + H;

    const float invB = 1.0f / (float)B;

    static bool attr_done = false;
    if (!attr_done) {
        cudaFuncSetAttribute(gemm_mma, cudaFuncAttributeMaxDynamicSharedMemorySize,
                             GEMM_SMEM);
        attr_done = true;
    }

    // 1) x conversion + partials  (r4 exact)
    convert_x<<<dim3(1, SPLITX), 256>>>(x);
    // 2) W scale + transpose      (r4 exact)
    convert_w<<<dim3(32, 32), dim3(32, 8)>>>(W, meta);
    // 3) GEMM (+ fused output column partials)
    dim3 ggrid(H / TN, B / TM);
    gemm_mma<<<ggrid, 256, GEMM_SMEM>>>(out);
    // 4) xmean + omean + STDP (warp-per-h)
    reduce_o_stdp<<<H_DIM / 8, 256>>>(pre, post, win, dec, invB);
    // 5) weights + meta + scalars + hist
    weights_meta_kernel<<<(H * H) / 1024, 256>>>(
        W, meta, act, ptr, target, hrate, mlr, out_w, out_meta, out_hist, ACT);
}